// round 4
// baseline (speedup 1.0000x reference)
#include <cuda_runtime.h>
#include <cuda_bf16.h>

// Seesaw loss, collapsed form:
//   denom[b] = sum_{j != t} s[t,j]*exp(l[b,j]) + exp(l[b,t])
//   loss[b]  = -log( exp(l[b,t]) / (denom + eps) + eps )
//   out      = mean_b loss[b]
// Shift-invariance of sigma makes row-max subtraction unnecessary.
//
// R4 changes vs R3:
//  - block-level pre-reduction: 2048 partials instead of 16384
//    (reduce kernel was 6.3us / 25% of runtime at 0.1% DRAM util)
//  - __ldcs (evict-first) on the logits stream so the 105MB one-pass
//    stream doesn't evict the ~10MB reused s-row working set from L2

#define C_CLASSES 1604
#define C_VEC (C_CLASSES / 4)   // 401 float4 per row
#define WARPS_PER_BLOCK 8
#define MAX_BLOCKS 4096
#define EPS 1e-6f

__device__ float g_block[MAX_BLOCKS];

__global__ __launch_bounds__(WARPS_PER_BLOCK * 32)
void seesaw_row_kernel(const float* __restrict__ logits,
                       const float* __restrict__ s,
                       const int* __restrict__ targets,
                       int B) {
    __shared__ float sh_loss[WARPS_PER_BLOCK];
    const int warp = threadIdx.x >> 5;
    const int lane = threadIdx.x & 31;
    const int b = blockIdx.x * WARPS_PER_BLOCK + warp;

    float loss = 0.0f;
    if (b < B) {
        const int t = targets[b];
        const float4* __restrict__ lrow = (const float4*)(logits + (size_t)b * C_CLASSES);
        const float4* __restrict__ wrow = (const float4*)(s + (size_t)t * C_CLASSES);

        float acc = 0.0f;
        #pragma unroll 4
        for (int v = lane; v < C_VEC; v += 32) {
            float4 l = __ldcs(lrow + v);   // streaming: no reuse, evict-first
            float4 w = __ldg(wrow + v);    // reused across batch: keep in L2
            acc = fmaf(w.x, __expf(l.x), acc);
            acc = fmaf(w.y, __expf(l.y), acc);
            acc = fmaf(w.z, __expf(l.z), acc);
            acc = fmaf(w.w, __expf(l.w), acc);
        }

        #pragma unroll
        for (int off = 16; off > 0; off >>= 1)
            acc += __shfl_xor_sync(0xFFFFFFFFu, acc, off);

        if (lane == 0) {
            float lt  = logits[(size_t)b * C_CLASSES + t];
            float et  = __expf(lt);
            float wtt = s[(size_t)t * C_CLASSES + t];
            float denom = acc - wtt * et + et;   // swap j==t weighted term for plain e^lt
            float sigma = et / (denom + EPS);
            loss = -logf(sigma + EPS);
        }
    }
    if (lane == 0) sh_loss[warp] = loss;
    __syncthreads();

    // warp 0 folds the block's 8 row-losses into one partial
    if (warp == 0) {
        float v = (lane < WARPS_PER_BLOCK) ? sh_loss[lane] : 0.0f;
        #pragma unroll
        for (int off = 4; off > 0; off >>= 1)
            v += __shfl_xor_sync(0xFFFFFFFFu, v, off);
        if (lane == 0) g_block[blockIdx.x] = v;
    }
}

__global__ __launch_bounds__(256)
void seesaw_reduce_kernel(float* __restrict__ out, int nblocks, int B) {
    __shared__ float sh[8];
    const int lane = threadIdx.x & 31;
    const int warp = threadIdx.x >> 5;

    float acc = 0.0f;
    // nblocks is a multiple of 4 in practice (2048); guard anyway
    const float4* p4 = (const float4*)g_block;
    int nvec = nblocks >> 2;
    for (int i = threadIdx.x; i < nvec; i += 256) {
        float4 v = p4[i];
        acc += v.x + v.y + v.z + v.w;
    }
    for (int i = (nvec << 2) + threadIdx.x; i < nblocks; i += 256)
        acc += g_block[i];

    #pragma unroll
    for (int off = 16; off > 0; off >>= 1)
        acc += __shfl_xor_sync(0xFFFFFFFFu, acc, off);
    if (lane == 0) sh[warp] = acc;
    __syncthreads();
    if (warp == 0) {
        float v = (lane < 8) ? sh[lane] : 0.0f;
        #pragma unroll
        for (int off = 4; off > 0; off >>= 1)
            v += __shfl_xor_sync(0xFFFFFFFFu, v, off);
        if (lane == 0) out[0] = v / (float)B;
    }
}

extern "C" void kernel_launch(void* const* d_in, const int* in_sizes, int n_in,
                              void* d_out, int out_size) {
    const float* logits  = (const float*)d_in[0];   // [B, C] f32
    const float* s       = (const float*)d_in[1];   // [C, C] f32
    const int*   targets = (const int*)d_in[2];     // [B] int32
    float* out = (float*)d_out;

    const int B = in_sizes[2];
    const int grid = (B + WARPS_PER_BLOCK - 1) / WARPS_PER_BLOCK;

    seesaw_row_kernel<<<grid, WARPS_PER_BLOCK * 32>>>(logits, s, targets, B);
    seesaw_reduce_kernel<<<1, 256>>>(out, grid, B);
}